// round 4
// baseline (speedup 1.0000x reference)
#include <cuda_runtime.h>
#include <math.h>
#include <float.h>

// Fixed problem shape: img (16,3,512,512) f32, sbin=4 -> out (16,31,128,128) f32
#define BATCH 16
#define NCH   3
#define IH    512
#define IW    512
#define BH    128
#define BW    128

#define TS    16          // output cells per tile side
#define HC    18          // halo cells per side (TS + 2)
#define NHC   (HC * HC)   // 324 halo cells
#define WR    76          // pixel window rows/cols (4*HC + 4)
#define NST   20          // 4-px strips per window row

__global__ __launch_bounds__(384, 2)
void hog_fused(const float* __restrict__ img, float* __restrict__ out) {
    __shared__ unsigned int s_pack[WR * WR];     // 23104 B : mag (hi bits) | bo (5 lo bits)
    __shared__ float        s_bins[18 * NHC];    // 23328 B
    __shared__ float        s_norm[NHC];         //  1296 B   (total 47728 B)

    const int tid = threadIdx.x;
    const int cx0 = blockIdx.x * TS;
    const int cy0 = blockIdx.y * TS;
    const int b   = blockIdx.z;

    const int wy0 = 4 * cy0 - 6;     // image row of window row 0
    const int wx0 = 4 * cx0 - 6;     // image col of window col 0
    const int x0a = 4 * cx0 - 8;     // aligned strip base (mult of 4)

    const float* base = img + (size_t)b * NCH * IH * IW;

    const float UU[9] = {1.0f, 0.9397f, 0.766f, 0.5f, 0.1736f,
                         -0.1736f, -0.5f, -0.766f, -0.9397f};
    const float VV[9] = {0.0f, 0.342f, 0.6428f, 0.866f, 0.9848f,
                         0.9848f, 0.866f, 0.6428f, 0.342f};

    // ---- zero own bins (only owner thread ever touches them) ----
    if (tid < NHC) {
#pragma unroll
        for (int o = 0; o < 18; o++) s_bins[o * NHC + tid] = 0.0f;
    }

    // ---- Stage 1: gradient / orientation for the pixel window ----
    for (int t = tid; t < NST * WR; t += 384) {
        const int s  = t % NST;
        const int py = t / NST;
        const int y  = wy0 + py;
        const int xb = x0a + 4 * s;

        unsigned int pk[4] = {0u, 0u, 0u, 0u};

        if (y >= 1 && y <= IH - 2 && xb >= 0 && xb <= IW - 4) {
            float bestv[4] = {-1.f, -1.f, -1.f, -1.f};
            float bdx[4], bdy[4];
#pragma unroll
            for (int c = 0; c < NCH; c++) {
                const float* rp = base + (size_t)c * IH * IW + (size_t)y * IW + xb;
                float4 up = *reinterpret_cast<const float4*>(rp - IW);
                float4 dn = *reinterpret_cast<const float4*>(rp + IW);
                float4 md = *reinterpret_cast<const float4*>(rp);
                float  lf = (xb >= 1) ? rp[-1] : 0.f;
                float  rt = (xb + 4 <= IW - 1) ? rp[4] : 0.f;
                float mx[6] = {lf, md.x, md.y, md.z, md.w, rt};
                float u[4]  = {up.x, up.y, up.z, up.w};
                float d[4]  = {dn.x, dn.y, dn.z, dn.w};
#pragma unroll
                for (int i = 0; i < 4; i++) {
                    float gdy = d[i] - u[i];
                    float gdx = mx[i + 2] - mx[i];
                    float v = gdx * gdx + gdy * gdy;
                    if (v > bestv[i]) { bestv[i] = v; bdx[i] = gdx; bdy[i] = gdy; }
                }
            }
#pragma unroll
            for (int i = 0; i < 4; i++) {
                float maxv = -FLT_MAX, minv = FLT_MAX;
                int   maxi = 0,        mini = 0;
#pragma unroll
                for (int k = 0; k < 9; k++) {
                    float dd = UU[k] * bdx[i] + VV[k] * bdy[i];
                    if (dd > maxv) { maxv = dd; maxi = k; }
                    if (dd < minv) { minv = dd; mini = k; }
                }
                int bo = (maxv >= -minv) ? maxi : mini + 9;
                float mag = (bestv[i] > 0.f) ? bestv[i] * rsqrtf(bestv[i]) : 0.f;
                int x = xb + i;
                if (x < 1 || x > IW - 2) mag = 0.f;
                pk[i] = (__float_as_uint(mag) & 0xFFFFFFE0u) | (unsigned)bo;
            }
        }
#pragma unroll
        for (int i = 0; i < 4; i++) {
            int sc = 4 * s - 2 + i;
            if (sc >= 0 && sc < WR) s_pack[py * WR + sc] = pk[i];
        }
    }

    __syncthreads();

    // ---- Stage 2: per-halo-cell 8x8 gather + norm (1 thread = 1 cell) ----
    const float W8[8] = {0.125f, 0.375f, 0.625f, 0.875f,
                         0.875f, 0.625f, 0.375f, 0.125f};

    if (tid < NHC) {
        const int hy = tid / HC;
        const int hx = tid - HC * hy;
        const int r0 = 4 * hy;
        const int c0 = 4 * hx;

#pragma unroll
        for (int dy = 0; dy < 8; dy++) {
            const float wy = W8[dy];
            const unsigned int* rowp = &s_pack[(r0 + dy) * WR + c0];
            uint4 p0 = *reinterpret_cast<const uint4*>(rowp);
            uint4 p1 = *reinterpret_cast<const uint4*>(rowp + 4);
            unsigned int uu[8] = {p0.x, p0.y, p0.z, p0.w, p1.x, p1.y, p1.z, p1.w};
#pragma unroll
            for (int dx = 0; dx < 8; dx++) {
                unsigned int u = uu[dx];
                float m = __uint_as_float(u & 0xFFFFFFE0u);
                int o = (int)(u & 31u);
                s_bins[o * NHC + tid] += m * (wy * W8[dx]);
            }
        }

        float acc = 0.0f;
#pragma unroll
        for (int o = 0; o < 9; o++) {
            float sv = s_bins[o * NHC + tid] + s_bins[(o + 9) * NHC + tid];
            acc += sv * sv;
        }
        s_norm[tid] = acc;
    }

    __syncthreads();

    // ---- Stage 3: features for the 16x16 output cells ----
    if (tid >= 256) return;

    const int ly = tid >> 4;
    const int lx = tid & 15;
    const int i = cy0 + ly;
    const int j = cx0 + lx;

    float* ob = out + (size_t)b * 31 * BH * BW + i * BW + j;

    if (i == 0 || i == BH - 1 || j == 0 || j == BW - 1) {
#pragma unroll
        for (int ch = 0; ch < 31; ch++) ob[ch * (BH * BW)] = 0.0f;
        return;
    }

    const float EPS = 0.0001f;
#define NM(a, c) s_norm[(ly + (a)) * HC + (lx + (c))]
    float n1 = rsqrtf(NM(1, 1) + NM(2, 1) + NM(1, 2) + NM(2, 2) + EPS);
    float n2 = rsqrtf(NM(0, 1) + NM(1, 1) + NM(0, 2) + NM(1, 2) + EPS);
    float n3 = rsqrtf(NM(1, 0) + NM(2, 0) + NM(1, 1) + NM(2, 1) + EPS);
    float n4 = rsqrtf(NM(0, 0) + NM(1, 0) + NM(0, 1) + NM(1, 1) + EPS);
#undef NM

    const int cell = (ly + 1) * HC + (lx + 1);
    float src[18];
#pragma unroll
    for (int o = 0; o < 18; o++) src[o] = s_bins[o * NHC + cell];

    float t1 = 0.f, t2 = 0.f, t3 = 0.f, t4 = 0.f;
#pragma unroll
    for (int o = 0; o < 18; o++) {
        float h1 = fminf(src[o] * n1, 0.2f);
        float h2 = fminf(src[o] * n2, 0.2f);
        float h3 = fminf(src[o] * n3, 0.2f);
        float h4 = fminf(src[o] * n4, 0.2f);
        t1 += h1; t2 += h2; t3 += h3; t4 += h4;
        ob[o * (BH * BW)] = 0.5f * (h1 + h2 + h3 + h4);
    }
#pragma unroll
    for (int o = 0; o < 9; o++) {
        float ss = src[o] + src[o + 9];
        float v = fminf(ss * n1, 0.2f) + fminf(ss * n2, 0.2f) +
                  fminf(ss * n3, 0.2f) + fminf(ss * n4, 0.2f);
        ob[(18 + o) * (BH * BW)] = 0.5f * v;
    }
    ob[27 * (BH * BW)] = 0.2357f * t1;
    ob[28 * (BH * BW)] = 0.2357f * t2;
    ob[29 * (BH * BW)] = 0.2357f * t3;
    ob[30 * (BH * BW)] = 0.2357f * t4;
}

// ---------------------------------------------------------------------------
extern "C" void kernel_launch(void* const* d_in, const int* in_sizes, int n_in,
                              void* d_out, int out_size) {
    const float* img = (const float*)d_in[0];
    float* out = (float*)d_out;

    dim3 grid(BW / TS, BH / TS, BATCH);   // (8, 8, 16)
    hog_fused<<<grid, 384>>>(img, out);
}

// round 5
// speedup vs baseline: 1.3802x; 1.3802x over previous
#include <cuda_runtime.h>
#include <math.h>
#include <float.h>

// Fixed problem shape: img (16,3,512,512) f32, sbin=4 -> out (16,31,128,128) f32
#define BATCH 16
#define NCH   3
#define IH    512
#define IW    512
#define BH    128
#define BW    128

#define TS     16         // cells per tile side
#define WROWS  68         // pixel rows in window
#define WCOLS  68         // pixel cols in window
#define MP     68         // smem pitch (u32), multiple of 4 for LDS.128
#define NSTRIP 18         // 4-px strips per row (covers sc -2..69)

#define HIST_ELEMS (BATCH * 18 * BH * BW)
#define NORM_ELEMS (BATCH * BH * BW)

__device__ float g_hist[HIST_ELEMS];
__device__ float g_norm[NORM_ELEMS];

// ---------------------------------------------------------------------------
// Kernel 1: gradients + orientation + per-cell gather + norm.
// One block = 16x16 cells. mag|bo packed in one u32 (bo in 5 low mantissa bits).
// ---------------------------------------------------------------------------
__global__ __launch_bounds__(256, 4) void hog_gather(const float* __restrict__ img) {
    __shared__ unsigned int s_pack[WROWS * MP];   // 18496 B
    __shared__ float        s_bins[18 * 256];     // 18432 B  (total 36928 B)

    const int tid = threadIdx.x;
    const int cx0 = blockIdx.x * TS;
    const int cy0 = blockIdx.y * TS;
    const int b   = blockIdx.z;

    const int y0  = 4 * cy0 - 2;        // image row of window row 0
    const int x0a = 4 * cx0 - 4;        // aligned image col of strip 0
    // smem col sc = image_x - (4*cx0 - 2)

    const float* base = img + (size_t)b * NCH * IH * IW;

    const float UU[9] = {1.0f, 0.9397f, 0.766f, 0.5f, 0.1736f,
                         -0.1736f, -0.5f, -0.766f, -0.9397f};
    const float VV[9] = {0.0f, 0.342f, 0.6428f, 0.866f, 0.9848f,
                         0.9848f, 0.866f, 0.6428f, 0.342f};

    // ---- zero per-thread bins (owner-only; sync below covers it) ----
#pragma unroll
    for (int o = 0; o < 18; o++) s_bins[o * 256 + tid] = 0.0f;

    // ---- Stage 1: per-pixel gradient / orientation, 4-px aligned strips ----
    for (int t = tid; t < NSTRIP * WROWS; t += 256) {
        const int s  = t % NSTRIP;
        const int py = t / NSTRIP;
        const int y  = y0 + py;
        const int xb = x0a + 4 * s;

        unsigned int pk[4] = {0u, 0u, 0u, 0u};

        if (y >= 1 && y <= IH - 2 && xb >= 0 && xb <= IW - 4) {
            float bestv[4] = {-1.f, -1.f, -1.f, -1.f};
            float bdx[4], bdy[4];
#pragma unroll
            for (int c = 0; c < NCH; c++) {
                const float* rp = base + (size_t)c * IH * IW + (size_t)y * IW + xb;
                float4 up = *reinterpret_cast<const float4*>(rp - IW);
                float4 dn = *reinterpret_cast<const float4*>(rp + IW);
                float4 md = *reinterpret_cast<const float4*>(rp);
                float  lf = (xb >= 1) ? rp[-1] : 0.f;
                float  rt = (xb + 4 <= IW - 1) ? rp[4] : 0.f;
                float mx[6] = {lf, md.x, md.y, md.z, md.w, rt};
                float u[4]  = {up.x, up.y, up.z, up.w};
                float d[4]  = {dn.x, dn.y, dn.z, dn.w};
#pragma unroll
                for (int i = 0; i < 4; i++) {
                    float gdy = d[i] - u[i];
                    float gdx = mx[i + 2] - mx[i];
                    float v = gdx * gdx + gdy * gdy;
                    if (v > bestv[i]) { bestv[i] = v; bdx[i] = gdx; bdy[i] = gdy; }
                }
            }
#pragma unroll
            for (int i = 0; i < 4; i++) {
                float maxv = -FLT_MAX, minv = FLT_MAX;
                int   maxi = 0,        mini = 0;
#pragma unroll
                for (int k = 0; k < 9; k++) {
                    float dd = UU[k] * bdx[i] + VV[k] * bdy[i];
                    if (dd > maxv) { maxv = dd; maxi = k; }
                    if (dd < minv) { minv = dd; mini = k; }
                }
                int bo = (maxv >= -minv) ? maxi : mini + 9;
                float mag = (bestv[i] > 0.f) ? bestv[i] * rsqrtf(bestv[i]) : 0.f;
                int x = xb + i;
                if (x < 1 || x > IW - 2) mag = 0.f;
                pk[i] = (__float_as_uint(mag) & 0xFFFFFFE0u) | (unsigned)bo;
            }
        }
#pragma unroll
        for (int i = 0; i < 4; i++) {
            int sc = 4 * s - 2 + i;
            if (sc >= 0 && sc < WCOLS) s_pack[py * MP + sc] = pk[i];
        }
    }

    __syncthreads();

    // ---- Stage 3: gather 8x8 pixel footprint per cell (1 thread = 1 cell) ----
    const int lcy = tid >> 4;
    const int lcx = tid & 15;
    const int pr  = 4 * lcy;
    const int pc  = 4 * lcx;

    const float W8[8] = {0.125f, 0.375f, 0.625f, 0.875f,
                         0.875f, 0.625f, 0.375f, 0.125f};

#pragma unroll
    for (int dy = 0; dy < 8; dy++) {
        const float wy = W8[dy];
        const unsigned int* rowp = &s_pack[(pr + dy) * MP + pc];
        uint4 p0 = *reinterpret_cast<const uint4*>(rowp);
        uint4 p1 = *reinterpret_cast<const uint4*>(rowp + 4);
        unsigned int uu[8] = {p0.x, p0.y, p0.z, p0.w, p1.x, p1.y, p1.z, p1.w};
#pragma unroll
        for (int dx = 0; dx < 8; dx++) {
            unsigned int u = uu[dx];
            float m = __uint_as_float(u & 0xFFFFFFE0u);
            int o = (int)(u & 31u);
            s_bins[o * 256 + tid] += m * (wy * W8[dx]);
        }
    }

    // ---- Stage 4: write hist + norm (coalesced stores) ----
    const int cy = cy0 + lcy;
    const int cx = cx0 + lcx;
    float* hb = g_hist + ((size_t)b * 18) * (BH * BW) + cy * BW + cx;

    float acc = 0.0f;
#pragma unroll
    for (int o = 0; o < 9; o++) {
        float a = s_bins[o * 256 + tid];
        float c = s_bins[(o + 9) * 256 + tid];
        hb[o * (BH * BW)]       = a;
        hb[(o + 9) * (BH * BW)] = c;
        float s = a + c;
        acc += s * s;
    }
    g_norm[(size_t)b * BH * BW + cy * BW + cx] = acc;
}

// ---------------------------------------------------------------------------
// Kernel 2: block-normalized features (31 channels), 1 px/thread (low regs)
// ---------------------------------------------------------------------------
__global__ void hog_feat(float* __restrict__ out) {
    int idx = blockIdx.x * blockDim.x + threadIdx.x;
    if (idx >= BATCH * BH * BW) return;
    int j = idx & (BW - 1);
    int t = idx >> 7;
    int i = t & (BH - 1);
    int b = t >> 7;

    float* ob = out + (size_t)b * 31 * BH * BW + i * BW + j;

    if (i == 0 || i == BH - 1 || j == 0 || j == BW - 1) {
#pragma unroll
        for (int ch = 0; ch < 31; ch++) ob[ch * (BH * BW)] = 0.0f;
        return;
    }

    const float* nb = g_norm + (size_t)b * BH * BW;
    const float EPS = 0.0001f;
#define NRM(a, c) nb[(a) * BW + (c)]
    float n1 = rsqrtf(NRM(i, j) + NRM(i + 1, j) + NRM(i, j + 1) + NRM(i + 1, j + 1) + EPS);
    float n2 = rsqrtf(NRM(i - 1, j) + NRM(i, j) + NRM(i - 1, j + 1) + NRM(i, j + 1) + EPS);
    float n3 = rsqrtf(NRM(i, j - 1) + NRM(i + 1, j - 1) + NRM(i, j) + NRM(i + 1, j) + EPS);
    float n4 = rsqrtf(NRM(i - 1, j - 1) + NRM(i, j - 1) + NRM(i - 1, j) + NRM(i, j) + EPS);
#undef NRM

    const float* hb = g_hist + (size_t)b * 18 * BH * BW + i * BW + j;

    float src[18];
#pragma unroll
    for (int o = 0; o < 18; o++) src[o] = hb[o * (BH * BW)];

    float t1 = 0.f, t2 = 0.f, t3 = 0.f, t4 = 0.f;
#pragma unroll
    for (int o = 0; o < 18; o++) {
        float h1 = fminf(src[o] * n1, 0.2f);
        float h2 = fminf(src[o] * n2, 0.2f);
        float h3 = fminf(src[o] * n3, 0.2f);
        float h4 = fminf(src[o] * n4, 0.2f);
        t1 += h1; t2 += h2; t3 += h3; t4 += h4;
        ob[o * (BH * BW)] = 0.5f * (h1 + h2 + h3 + h4);
    }
#pragma unroll
    for (int o = 0; o < 9; o++) {
        float ss = src[o] + src[o + 9];
        float v = fminf(ss * n1, 0.2f) + fminf(ss * n2, 0.2f) +
                  fminf(ss * n3, 0.2f) + fminf(ss * n4, 0.2f);
        ob[(18 + o) * (BH * BW)] = 0.5f * v;
    }
    ob[27 * (BH * BW)] = 0.2357f * t1;
    ob[28 * (BH * BW)] = 0.2357f * t2;
    ob[29 * (BH * BW)] = 0.2357f * t3;
    ob[30 * (BH * BW)] = 0.2357f * t4;
}

// ---------------------------------------------------------------------------
extern "C" void kernel_launch(void* const* d_in, const int* in_sizes, int n_in,
                              void* d_out, int out_size) {
    const float* img = (const float*)d_in[0];
    float* out = (float*)d_out;

    dim3 grid(BW / TS, BH / TS, BATCH);   // (8, 8, 16)
    hog_gather<<<grid, 256>>>(img);

    int n = BATCH * BH * BW;
    hog_feat<<<(n + 255) / 256, 256>>>(out);
}